// round 1
// baseline (speedup 1.0000x reference)
#include <cuda_runtime.h>
#include <math.h>

// DenseHyperbolic fused kernel.
// Analytic reduction of the reference:
//   tangent = m(Sv) * v (col0 zeroed);  g = v' @ W
//   everything downstream is per-row scalars of Sg = sum_{j>=1} g_j^2,
//   dg = sum_{j>=1} g_j*bias_j, Sb = sum bias^2:
//   out_j = Aw*g_j + Ab*bias_j  (j>=1),  out_0 = sqrt(c2)*cosh(nf_clipped)
// One fused GEMM (131072x256x256 fp32) + epilogue. FFMA2 (fma.rn.f32x2)
// for full Blackwell fp32 rate (3-reg FFMA is half-rate on sm_10x).

constexpr int D  = 256;
constexpr int BM = 64;
constexpr int BK = 16;
constexpr int NT = 256;

#define EPSF       1e-4f
#define ACOSH_MINF 1.0001f
#define CLIPF      8.0f

typedef unsigned long long u64;

__device__ __forceinline__ u64 pack2(float x, float y) {
    u64 r; asm("mov.b64 %0, {%1, %2};" : "=l"(r) : "f"(x), "f"(y)); return r;
}
__device__ __forceinline__ void unpack2(u64 v, float& x, float& y) {
    asm("mov.b64 {%0, %1}, %2;" : "=f"(x), "=f"(y) : "l"(v));
}
__device__ __forceinline__ void ffma2(u64& d, u64 a, u64 b) {
    asm("fma.rn.f32x2 %0, %1, %2, %0;" : "+l"(d) : "l"(a), "l"(b));
}

__global__ __launch_bounds__(NT, 2)
void dh_kernel(const float* __restrict__ V,
               const float* __restrict__ cin_p,
               const float* __restrict__ cout_p,
               const float* __restrict__ W,
               const float* __restrict__ bias,
               float* __restrict__ out, int B)
{
    __shared__ float sA[BM][BK + 1];   // +1 pad: kills 2-way LDS conflicts
    __shared__ float sW[BK][D];
    __shared__ float sbias[D];
    __shared__ float svsum[BM];
    __shared__ float sSbArr[8];
    __shared__ float sSb;

    const int tid  = threadIdx.x;
    const int row0 = blockIdx.x * BM;
    if (row0 >= B) return;

    // bias -> smem (index 0 is the zero time-coordinate), Sb = sum(bias^2)
    {
        float bv = (tid == 0) ? 0.f : __ldg(&bias[tid - 1]);
        sbias[tid] = bv;
        float sq = bv * bv;
        #pragma unroll
        for (int o = 16; o > 0; o >>= 1) sq += __shfl_xor_sync(0xFFFFFFFFu, sq, o);
        if ((tid & 31) == 0) sSbArr[tid >> 5] = sq;
    }
    __syncthreads();
    if (tid == 0) {
        float s = 0.f;
        #pragma unroll
        for (int i = 0; i < 8; i++) s += sSbArr[i];
        sSb = s;
    }

    const int rg   = tid >> 4;   // row group: rows rg*4 .. rg*4+3
    const int tx   = tid & 15;   // column lane: col pairs {2*tx + 32*j}
    const int arow = tid >> 2;   // A-load row
    const int ac4  = tid & 3;    // A-load float4 slot within k-tile

    u64 acc[4][8];
    #pragma unroll
    for (int i = 0; i < 4; i++)
        #pragma unroll
        for (int j = 0; j < 8; j++) acc[i][j] = 0ull;

    float svloc = 0.f;   // partial sum of v_i^2 (i>=1) for row `arow`

    for (int kt = 0; kt < D / BK; ++kt) {
        const int k0 = kt * BK;
        __syncthreads();
        // A tile [64 x 16]: one float4 per thread; zero the time coord.
        {
            float4 a = *reinterpret_cast<const float4*>(
                V + (size_t)(row0 + arow) * D + k0 + ac4 * 4);
            if (kt == 0 && ac4 == 0) a.x = 0.f;
            svloc += a.x * a.x + a.y * a.y + a.z * a.z + a.w * a.w;
            sA[arow][ac4 * 4 + 0] = a.x;
            sA[arow][ac4 * 4 + 1] = a.y;
            sA[arow][ac4 * 4 + 2] = a.z;
            sA[arow][ac4 * 4 + 3] = a.w;
        }
        // W tile [16 x 256]: 4 float4 per thread, coalesced, L2-resident.
        #pragma unroll
        for (int l = 0; l < 4; ++l) {
            int p  = tid + l * NT;
            int wr = p >> 6;
            int wc = (p & 63) * 4;
            *reinterpret_cast<float4*>(&sW[wr][wc]) =
                *reinterpret_cast<const float4*>(W + (size_t)(k0 + wr) * D + wc);
        }
        __syncthreads();
        // Compute: 4 rows x 8 col-pairs per thread, packed f32x2 FMAs.
        #pragma unroll
        for (int kk = 0; kk < BK; ++kk) {
            u64 a2[4];
            #pragma unroll
            for (int i = 0; i < 4; ++i) {
                float a = sA[rg * 4 + i][kk];
                a2[i] = pack2(a, a);
            }
            #pragma unroll
            for (int j = 0; j < 8; ++j) {
                u64 w2 = *reinterpret_cast<const u64*>(&sW[kk][2 * tx + 32 * j]);
                #pragma unroll
                for (int i = 0; i < 4; ++i) ffma2(acc[i][j], a2[i], w2);
            }
        }
    }

    // Reduce Sv partials (4 lanes per row, deterministic shuffle tree).
    svloc += __shfl_xor_sync(0xFFFFFFFFu, svloc, 1);
    svloc += __shfl_xor_sync(0xFFFFFFFFu, svloc, 2);
    if (ac4 == 0) svsum[arow] = svloc;
    __syncthreads();

    const float c   = *cin_p;
    const float c2  = *cout_p;
    const float sqc = sqrtf(c);
    const float sq2 = sqrtf(c2);
    const float Sb  = sSb;

    #pragma unroll
    for (int i = 0; i < 4; ++i) {
        const int row = rg * 4 + i;
        float Sg = 0.f, dg = 0.f;
        #pragma unroll
        for (int j = 0; j < 8; ++j) {
            float glo, ghi;
            unpack2(acc[i][j], glo, ghi);
            int col = 2 * tx + 32 * j;
            float blo = sbias[col];
            float bhi = sbias[col + 1];
            if (col != 0) {           // exclude masked time column
                Sg = fmaf(glo, glo, Sg);
                dg = fmaf(glo, blo, dg);
            }
            Sg = fmaf(ghi, ghi, Sg);
            dg = fmaf(ghi, bhi, dg);
        }
        // Butterfly across the 16 lanes covering this row.
        #pragma unroll
        for (int o = 8; o > 0; o >>= 1) {
            Sg += __shfl_xor_sync(0xFFFFFFFFu, Sg, o);
            dg += __shfl_xor_sync(0xFFFFFFFFu, dg, o);
        }

        // ---- per-row scalar chain (exact reduction of the reference) ----
        const float Sv   = svsum[row];
        const float v0p  = sqrtf(c + Sv);
        const float m    = (sqc * acoshf(fmaxf(v0p / sqc - EPSF, ACOSH_MINF)))
                           / (sqrtf(Sv) + EPSF);              // logmap multiplier
        const float Sw   = m * m * Sg;                        // ||w||^2
        const float dw   = m * dg;                            // inner_hyper(w, bias)
        const float n    = sqrtf(Sw) / sqc + EPSF;
        const float ncl  = fminf(n, CLIPF);
        const float ch   = coshf(ncl);
        const float sfac = sinhf(ncl) / n;                    // h_j = sfac * w_j
        const float T    = sfac * sfac * Sw;                  // sum h_j^2
        const float hp0  = sqrtf(c + T);                      // projected h time coord
        const float dd   = sqc * acoshf(fmaxf(ch, ACOSH_MINF));           // distance
        const float d2   = sqc * acoshf(fmaxf(hp0 / sqc - EPSF, ACOSH_MINF));
        const float u0   = sqc - hp0 * hp0 / sqc;
        const float suj2 = (hp0 * hp0 / c) * T;
        const float nrmu = sqrtf(suj2 - u0 * u0);
        const float mlt  = d2 / (nrmu + EPSF);
        const float alph = 1.f - mlt * (hp0 / sqc) * sfac;    // s_j = alph * w_j
        const float m2   = dw / (dd * dd);
        const float beta = alph * m2;
        const float bt0  = -(mlt * u0) * m2;
        const float btsq = bt0 * bt0 + Sb - 2.f * beta * dw + beta * beta * Sw;
        const float nb   = sqrtf(btsq) / sqc + EPSF;
        const float nbcl = fminf(nb, CLIPF);
        const float chb  = coshf(nbcl);
        const float sfb  = sinhf(nbcl) / nb;
        const float gam  = chb * sfac - sfb * beta;           // biased_j = gam*w_j + del*bias_j
        const float del  = sfb;
        const float Sbi  = gam * gam * Sw + 2.f * gam * del * dw + del * del * Sb;
        const float p0   = sqrtf(c + Sbi);
        const float d3   = sqc * acoshf(fmaxf(p0 / sqc - EPSF, ACOSH_MINF));
        const float q    = sqrtf(Sbi);
        const float mlt3 = d3 / (q + EPSF);
        const float nf   = mlt3 * q / sq2 + EPSF;
        const float nfcl = fminf(nf, CLIPF);
        const float phi  = (sinhf(nfcl) / nf) * mlt3;
        const float Aw   = phi * gam * m;                     // coeff on g_j
        const float Ab   = phi * del;                         // coeff on bias_j
        const float out0 = sq2 * coshf(nfcl);

        float* orow = out + (size_t)(row0 + row) * D;
        #pragma unroll
        for (int j = 0; j < 8; ++j) {
            float glo, ghi;
            unpack2(acc[i][j], glo, ghi);
            int col = 2 * tx + 32 * j;
            float2 o2;
            o2.x = (col == 0) ? out0 : fmaf(Aw, glo, Ab * sbias[col]);
            o2.y = fmaf(Aw, ghi, Ab * sbias[col + 1]);
            *reinterpret_cast<float2*>(orow + col) = o2;
        }
    }
}

extern "C" void kernel_launch(void* const* d_in, const int* in_sizes, int n_in,
                              void* d_out, int out_size)
{
    const float* V    = (const float*)d_in[0];
    const float* cin  = (const float*)d_in[1];
    const float* cout = (const float*)d_in[2];
    const float* W    = (const float*)d_in[3];
    const float* bias = (const float*)d_in[4];
    float* out = (float*)d_out;

    const int B = in_sizes[0] / D;          // 131072
    dim3 grid((B + BM - 1) / BM);           // 2048 blocks
    dh_kernel<<<grid, NT>>>(V, cin, cout, W, bias, out, B);
}